// round 1
// baseline (speedup 1.0000x reference)
#include <cuda_runtime.h>

// Problem constants
#define N_ 4
#define C_ 128
#define T_ 512
#define V_ 25
#define H_ 16
#define O_ 128
#define EPS_ 1e-5f
#define YCNT 51200.0f   // N*T*V

typedef unsigned long long ull;

// ---------------- scratch (device globals; no allocation allowed) ----------
__device__ float g_q[N_ * T_ * H_];          // [n][t][h]
__device__ float g_k[N_ * T_ * H_];          // [n][t][h]
__device__ float g_wvt[C_ * O_];             // [c][o]  (Wv transposed)
__device__ float g_v[N_ * T_ * O_ * 32];     // [n][t][o][32] (25 data + 7 zero pad)
__device__ float g_vsum[N_ * O_ * 32];       // [n][o][32] sum over t (pads zero)
__device__ float g_y[N_ * O_ * T_ * V_];     // [n][o][g][v]
__device__ float g_chsum[O_];
__device__ float g_chsq[O_];

// ---------------- f32x2 / tanh helpers -------------------------------------
__device__ __forceinline__ ull ffma2(ull a, ull b, ull c) {
    ull d; asm("fma.rn.f32x2 %0, %1, %2, %3;" : "=l"(d) : "l"(a), "l"(b), "l"(c)); return d;
}
__device__ __forceinline__ ull fmul2(ull a, ull b) {
    ull d; asm("mul.rn.f32x2 %0, %1, %2;" : "=l"(d) : "l"(a), "l"(b)); return d;
}
__device__ __forceinline__ ull dup2(float x) {
    ull d; asm("mov.b64 %0, {%1, %1};" : "=l"(d) : "f"(x)); return d;
}
__device__ __forceinline__ float2 unpack2(ull a) {
    float2 r; asm("mov.b64 {%0, %1}, %2;" : "=f"(r.x), "=f"(r.y) : "l"(a)); return r;
}
__device__ __forceinline__ float tanh_fast(float x) {
    float r; asm("tanh.approx.f32 %0, %1;" : "=f"(r) : "f"(x)); return r;
}

// ---------------- K0: transpose Wv -> g_wvt[c][o] ---------------------------
__global__ void wt_kernel(const float* __restrict__ Wv) {
    int i = blockIdx.x * 256 + threadIdx.x;   // 16384 total
    int o = i >> 7, c = i & 127;
    g_wvt[c * O_ + o] = Wv[i];
}

// ---------------- K1: xm = mean_v(x); q,k = W@xm + b ------------------------
// block = (n,t), 128 threads
__global__ void qk_kernel(const float* __restrict__ x,
                          const float* __restrict__ Wq, const float* __restrict__ bq,
                          const float* __restrict__ Wk, const float* __restrict__ bk) {
    __shared__ float xm[C_];
    int b = blockIdx.x; int n = b >> 9; int t = b & 511;
    int c = threadIdx.x;
    const float* xp = x + ((n * C_ + c) * T_ + t) * V_;
    float s = 0.f;
#pragma unroll
    for (int v = 0; v < V_; v++) s += xp[v];
    xm[c] = s * (1.0f / 25.0f);
    __syncthreads();
    if (threadIdx.x < 32) {
        int h = threadIdx.x & 15;
        bool isQ = threadIdx.x < 16;
        const float* W = isQ ? Wq : Wk;
        float acc = isQ ? bq[h] : bk[h];
#pragma unroll 8
        for (int cc = 0; cc < C_; cc++) acc += W[h * C_ + cc] * xm[cc];
        float* dst = isQ ? g_q : g_k;
        dst[(n * T_ + t) * H_ + h] = acc;   // [n][t][h] layout
    }
}

// ---------------- K2: v[n][t][o][.] = Wv @ x + bv ---------------------------
// block = (n,t), 128 threads (thread = o)
__global__ void v_kernel(const float* __restrict__ x, const float* __restrict__ bv) {
    __shared__ float xs[C_][28];
    int b = blockIdx.x; int n = b >> 9; int t = b & 511;
    int o = threadIdx.x;
    {   // thread loads x[n][c=o][t][:]
        const float* xp = x + ((n * C_ + o) * T_ + t) * V_;
#pragma unroll
        for (int v = 0; v < V_; v++) xs[o][v] = xp[v];
        xs[o][25] = 0.f; xs[o][26] = 0.f; xs[o][27] = 0.f;
    }
    __syncthreads();
    float bvo = bv[o];
    ull acc[13];
    ull binit = dup2(bvo);
#pragma unroll
    for (int j = 0; j < 13; j++) acc[j] = binit;
    for (int c = 0; c < C_; c++) {
        float w = g_wvt[c * O_ + o];           // coalesced
        ull wd = dup2(w);
        const ull* xr = (const ull*)xs[c];     // 112B row offset: 8B aligned
#pragma unroll
        for (int j = 0; j < 13; j++) acc[j] = ffma2(wd, xr[j], acc[j]);
    }
    float* row = g_v + (((size_t)(n * T_ + t)) * O_ + o) * 32;
#pragma unroll
    for (int j = 0; j < 12; j++) {
        float2 u = unpack2(acc[j]);
        row[2 * j] = u.x; row[2 * j + 1] = u.y;
    }
    { float2 u = unpack2(acc[12]); row[24] = u.x; }
#pragma unroll
    for (int p = 25; p < 32; p++) row[p] = 0.f;
}

// ---------------- K2b: Vsum[n][o][.] = sum_t v -------------------------------
// block = (n,o), 128 threads
__global__ void vsum_kernel() {
    __shared__ float red[32];
    int n = blockIdx.x >> 7; int o = blockIdx.x & 127;
    int tid = threadIdx.x;
    if (tid < 32) red[tid] = 0.f;
    __syncthreads();
    float loc[26];
#pragma unroll
    for (int j = 0; j < 26; j++) loc[j] = 0.f;
    for (int t = tid; t < T_; t += 128) {
        const float* vp = g_v + (((size_t)(n * T_ + t)) * O_ + o) * 32;
#pragma unroll
        for (int j = 0; j < 26; j++) loc[j] += vp[j];
    }
#pragma unroll
    for (int j = 0; j < 26; j++) atomicAdd(&red[j], loc[j]);
    __syncthreads();
    if (tid < 32) g_vsum[(n * O_ + o) * 32 + tid] = (tid < 26) ? red[tid] : 0.f;
}

// ---------------- K2c: zero BN stat accumulators ----------------------------
__global__ void zero_kernel() {
    int i = threadIdx.x;
    if (i < O_) g_chsum[i] = 0.f;
    else if (i < 2 * O_) g_chsq[i - O_] = 0.f;
}

// ---------------- K3: fused attention main kernel ---------------------------
// block = (n, o_block of 16, g_block of 32), 512 threads, thread = one (o,g)
// dyn smem: k_s[512][16] | q_s[32][16] | S_s[32][16][16] | v_s[16][16][34]
#define OB 16
#define GB 32
#define TCH 16
#define SM_K   0
#define SM_Q   (T_ * H_)                 // 8192
#define SM_S   (SM_Q + GB * H_)          // 8704
#define SM_V   (SM_S + GB * TCH * H_)    // 16896
#define SM_FLOATS (SM_V + TCH * OB * 34) // 25600 -> 102400 bytes

__global__ void __launch_bounds__(512)
attn_kernel(const float* __restrict__ Wr, const float* __restrict__ br) {
    extern __shared__ float sm[];
    float* k_s = sm + SM_K;
    float* q_s = sm + SM_Q;
    float* S_s = sm + SM_S;
    float* v_s = sm + SM_V;

    int bx = blockIdx.x;
    int n  = bx >> 7;
    int ob = (bx >> 4) & 7;
    int gb = bx & 15;
    int o_base = ob * OB, g_base = gb * GB;
    int tid = threadIdx.x;
    int o_l = tid & 15, g_l = tid >> 4;
    int o0 = o_base + o_l;
    int g  = g_base + g_l;

    // load k_s (full [t][h] slice, coalesced)
    const float* kg = g_k + n * T_ * H_;
    for (int i = tid; i < T_ * H_; i += 512) k_s[i] = kg[i];
    // load q_s[g][h]
    const float* qg = g_q + (n * T_ + g_base) * H_;
    if (tid < GB * H_) q_s[tid] = qg[tid];

    // Wr row as 8 packed f32x2
    ull w[8];
    {
        const ull* wp = (const ull*)(Wr + o0 * H_);
#pragma unroll
        for (int j = 0; j < 8; j++) w[j] = wp[j];
    }
    // acc init: br[o] * Vsum
    ull acc[13];
    {
        float br0 = br[o0];
        ull brd = dup2(br0);
        const ull* vs = (const ull*)(g_vsum + (n * O_ + o0) * 32);
#pragma unroll
        for (int j = 0; j < 13; j++) acc[j] = fmul2(brd, vs[j]);
    }
    __syncthreads();

    for (int t0 = 0; t0 < T_; t0 += TCH) {
        // Phase A: S_s[g][tt][h] = tanh(q[g][h] - k[t0+tt][h])   (8192 items)
#pragma unroll
        for (int it = 0; it < 16; it++) {
            int item = tid + it * 512;
            int h  = item & 15;
            int tt = (item >> 4) & 15;
            int gg = item >> 8;
            float d = q_s[gg * H_ + h] - k_s[(t0 + tt) * H_ + h];
            S_s[(gg * TCH + tt) * H_ + h] = tanh_fast(d);
        }
        // Phase V: copy v chunk -> v_s[tt][o][34] (13 float2 each, 2 thr/row)
        {
            int pair = tid >> 1, half = tid & 1;
            int oo = pair & 15, tt = pair >> 4;
            const float2* src = (const float2*)(g_v + (((size_t)(n * T_ + t0 + tt)) * O_ + o_base + oo) * 32);
            float2* dst = (float2*)(v_s + (tt * OB + oo) * 34);
            for (int j = half; j < 13; j += 2) dst[j] = src[j];
        }
        __syncthreads();

        // Phase C: accumulate
#pragma unroll
        for (int tt = 0; tt < TCH; tt++) {
            const ull* sp = (const ull*)(S_s + (g_l * TCH + tt) * H_);
            ull a = 0ULL;  // (0.f,0.f)
#pragma unroll
            for (int j = 0; j < 8; j++) a = ffma2(w[j], sp[j], a);
            float2 au = unpack2(a);
            float A = au.x + au.y;
            ull Ad = dup2(A);
            const ull* vp = (const ull*)(v_s + (tt * OB + o_l) * 34);
#pragma unroll
            for (int j = 0; j < 13; j++) acc[j] = ffma2(Ad, vp[j], acc[j]);
        }
        __syncthreads();
    }

    // epilogue: write y + BN partial stats
    float sum = 0.f, sq = 0.f;
    float* yp = g_y + (((size_t)(n * O_ + o0)) * T_ + g) * V_;
#pragma unroll
    for (int j = 0; j < 12; j++) {
        float2 u = unpack2(acc[j]);
        yp[2 * j] = u.x; yp[2 * j + 1] = u.y;
        sum += u.x + u.y; sq += u.x * u.x + u.y * u.y;
    }
    {
        float2 u = unpack2(acc[12]);
        yp[24] = u.x; sum += u.x; sq += u.x * u.x;
    }
    atomicAdd(&g_chsum[o0], sum);
    atomicAdd(&g_chsq[o0], sq);
}

// ---------------- K4: BatchNorm + residual + ReLU ----------------------------
__global__ void bn_kernel(const float* __restrict__ x,
                          const float* __restrict__ gamma, const float* __restrict__ beta,
                          float* __restrict__ out) {
    int idx = blockIdx.x * 256 + threadIdx.x;
    if (idx >= N_ * O_ * T_ * V_) return;
    int o = (idx / (T_ * V_)) & 127;
    float mu  = g_chsum[o] * (1.0f / YCNT);
    float var = g_chsq[o] * (1.0f / YCNT) - mu * mu;
    float r = rsqrtf(var + EPS_);
    float yv = (g_y[idx] - mu) * r * gamma[o] + beta[o];
    float res = yv + x[idx];
    out[idx] = res > 0.f ? res : 0.f;
}

// ---------------- launcher ---------------------------------------------------
extern "C" void kernel_launch(void* const* d_in, const int* in_sizes, int n_in,
                              void* d_out, int out_size) {
    const float* x     = (const float*)d_in[0];
    const float* Wq    = (const float*)d_in[1];
    const float* bq    = (const float*)d_in[2];
    const float* Wk    = (const float*)d_in[3];
    const float* bk    = (const float*)d_in[4];
    const float* Wv    = (const float*)d_in[5];
    const float* bv    = (const float*)d_in[6];
    const float* Wr    = (const float*)d_in[7];
    const float* br    = (const float*)d_in[8];
    const float* gamma = (const float*)d_in[9];
    const float* beta  = (const float*)d_in[10];
    float* out = (float*)d_out;

    static_assert(SM_FLOATS == 25600, "smem layout");
    const int smem_bytes = SM_FLOATS * 4;  // 102400
    cudaFuncSetAttribute(attn_kernel, cudaFuncAttributeMaxDynamicSharedMemorySize, smem_bytes);

    wt_kernel<<<64, 256>>>(Wv);
    qk_kernel<<<N_ * T_, 128>>>(x, Wq, bq, Wk, bk);
    v_kernel<<<N_ * T_, 128>>>(x, bv);
    vsum_kernel<<<N_ * O_, 128>>>();
    zero_kernel<<<1, 256>>>();
    attn_kernel<<<N_ * 8 * 16, 512, smem_bytes>>>(Wr, br);
    bn_kernel<<<(N_ * O_ * T_ * V_ + 255) / 256, 256>>>(x, gamma, beta, out);
}

// round 2
// speedup vs baseline: 1.2113x; 1.2113x over previous
#include <cuda_runtime.h>

#define N_ 4
#define C_ 128
#define T_ 512
#define V_ 25
#define H_ 16
#define O_ 128
#define EPS_ 1e-5f
#define YCNT 51200.0f   // N*T*V

typedef unsigned long long ull;

// ---------------- scratch ----------------------------------------------------
__device__ float g_q[N_ * T_ * H_];          // [n][t][h]
__device__ float g_k[N_ * T_ * H_];          // [n][t][h]
__device__ float g_wvt[C_ * O_];             // [c][o]
__device__ float g_v[N_ * T_ * O_ * 32];     // [n][t][o][32] (25 data + zeros)
__device__ float g_vsum[N_ * O_ * 32];       // [n][o][32]
__device__ float g_y[N_ * O_ * T_ * 26];     // [n][o][g][26] (25 data + 1 pad)
__device__ float g_chsum[O_];
__device__ float g_chsq[O_];

// ---------------- helpers -----------------------------------------------------
__device__ __forceinline__ ull ffma2(ull a, ull b, ull c) {
    ull d; asm("fma.rn.f32x2 %0, %1, %2, %3;" : "=l"(d) : "l"(a), "l"(b), "l"(c)); return d;
}
__device__ __forceinline__ ull fmul2(ull a, ull b) {
    ull d; asm("mul.rn.f32x2 %0, %1, %2;" : "=l"(d) : "l"(a), "l"(b)); return d;
}
__device__ __forceinline__ ull fadd2(ull a, ull b) {
    ull d; asm("add.rn.f32x2 %0, %1, %2;" : "=l"(d) : "l"(a), "l"(b)); return d;
}
__device__ __forceinline__ ull dup2(float x) {
    ull d; asm("mov.b64 %0, {%1, %1};" : "=l"(d) : "f"(x)); return d;
}
__device__ __forceinline__ float2 unpack2(ull a) {
    float2 r; asm("mov.b64 {%0, %1}, %2;" : "=f"(r.x), "=f"(r.y) : "l"(a)); return r;
}
__device__ __forceinline__ float tanh_fast(float x) {
    float r; asm("tanh.approx.f32 %0, %1;" : "=f"(r) : "f"(x)); return r;
}
__device__ __forceinline__ void cp16(float* dst, const float* src) {
    unsigned du = (unsigned)__cvta_generic_to_shared(dst);
    asm volatile("cp.async.ca.shared.global [%0], [%1], 16;" :: "r"(du), "l"(src));
}
#define CP_COMMIT() asm volatile("cp.async.commit_group;")
#define CP_WAIT0()  asm volatile("cp.async.wait_group 0;")

// ---------------- K0: transpose Wv ------------------------------------------
__global__ void wt_kernel(const float* __restrict__ Wv) {
    int i = blockIdx.x * 256 + threadIdx.x;
    int o = i >> 7, c = i & 127;
    g_wvt[c * O_ + o] = Wv[i];
}

// ---------------- K1: q,k ------------------------------------------------------
__global__ void qk_kernel(const float* __restrict__ x,
                          const float* __restrict__ Wq, const float* __restrict__ bq,
                          const float* __restrict__ Wk, const float* __restrict__ bk) {
    __shared__ float xm[C_];
    int b = blockIdx.x; int n = b >> 9; int t = b & 511;
    int c = threadIdx.x;
    const float* xp = x + ((n * C_ + c) * T_ + t) * V_;
    float s = 0.f;
#pragma unroll
    for (int v = 0; v < V_; v++) s += xp[v];
    xm[c] = s * (1.0f / 25.0f);
    __syncthreads();
    if (threadIdx.x < 32) {
        int h = threadIdx.x & 15;
        bool isQ = threadIdx.x < 16;
        const float* W = isQ ? Wq : Wk;
        float acc = isQ ? bq[h] : bk[h];
#pragma unroll 8
        for (int cc = 0; cc < C_; cc++) acc += W[h * C_ + cc] * xm[cc];
        float* dst = isQ ? g_q : g_k;
        dst[(n * T_ + t) * H_ + h] = acc;
    }
}

// ---------------- K2: v projection --------------------------------------------
__global__ void v_kernel(const float* __restrict__ x, const float* __restrict__ bv) {
    __shared__ float xs[C_][28];
    int b = blockIdx.x; int n = b >> 9; int t = b & 511;
    int o = threadIdx.x;
    {
        const float* xp = x + ((n * C_ + o) * T_ + t) * V_;
#pragma unroll
        for (int v = 0; v < V_; v++) xs[o][v] = xp[v];
        xs[o][25] = 0.f; xs[o][26] = 0.f; xs[o][27] = 0.f;
    }
    __syncthreads();
    float bvo = bv[o];
    ull acc[13];
    ull binit = dup2(bvo);
#pragma unroll
    for (int j = 0; j < 13; j++) acc[j] = binit;
    for (int c = 0; c < C_; c++) {
        float w = g_wvt[c * O_ + o];
        ull wd = dup2(w);
        const ull* xr = (const ull*)xs[c];
#pragma unroll
        for (int j = 0; j < 13; j++) acc[j] = ffma2(wd, xr[j], acc[j]);
    }
    float* row = g_v + (((size_t)(n * T_ + t)) * O_ + o) * 32;
#pragma unroll
    for (int j = 0; j < 12; j++) {
        float2 u = unpack2(acc[j]);
        row[2 * j] = u.x; row[2 * j + 1] = u.y;
    }
    { float2 u = unpack2(acc[12]); row[24] = u.x; }
#pragma unroll
    for (int p = 25; p < 32; p++) row[p] = 0.f;
}

// ---------------- K2b: coalesced vsum ------------------------------------------
// 64 blocks = (n 4, o-chunk 16 of 8), 256 threads = 8 o x 32 comps
__global__ void vsum_kernel() {
    int bx = blockIdx.x;
    int n = bx >> 4, oc = bx & 15;
    int o = oc * 8 + (threadIdx.x >> 5);
    int comp = threadIdx.x & 31;
    const float* base = g_v + (((size_t)n * T_) * O_ + o) * 32 + comp;
    float a0 = 0.f, a1 = 0.f;
    for (int t = 0; t < T_; t += 16) {
        float l[16];
#pragma unroll
        for (int u = 0; u < 16; u++) l[u] = base[(size_t)(t + u) * O_ * 32];
#pragma unroll
        for (int u = 0; u < 16; u += 2) { a0 += l[u]; a1 += l[u + 1]; }
    }
    g_vsum[(n * O_ + o) * 32 + comp] = a0 + a1;
}

__global__ void zero_kernel() {
    int i = threadIdx.x;
    if (i < O_) g_chsum[i] = 0.f;
    else if (i < 2 * O_) g_chsq[i - O_] = 0.f;
}

// ---------------- K3: fused attention -------------------------------------------
#define OB 16
#define GBL 32
#define TCH 16
#define NCHUNK (T_ / TCH)
#define SM_KS 0
#define SM_QS (SM_KS + T_ * H_)            // 8192
#define SM_SS (SM_QS + GBL * H_)           // 8704
#define SM_VS (SM_SS + 2 * GBL * TCH * H_) // 25088
#define SM_TOT (SM_VS + 2 * TCH * OB * 28) // 39424 floats = 157696 B
#define S_BUF (GBL * TCH * H_)             // 8192
#define V_BUF (TCH * OB * 28)              // 7168

__device__ __forceinline__ void cp_v_chunk(int n, int o_base, int c, float* dst) {
    int tid = threadIdx.x;
    const float* src_base = g_v + (((size_t)(n * T_ + c * TCH)) * O_ + o_base) * 32;
    for (int i = tid; i < TCH * OB * 7; i += 512) {
        int r = i / 7, j = i - r * 7;
        int tt = r >> 4, oo = r & 15;
        const float* s = src_base + ((size_t)tt * O_ + oo) * 32 + j * 4;
        float* d = dst + (tt * OB + oo) * 28 + j * 4;
        cp16(d, s);
    }
}

__global__ void __launch_bounds__(512, 1)
attn_kernel(const float* __restrict__ Wr, const float* __restrict__ br) {
    extern __shared__ float sm[];
    float* k_s = sm + SM_KS;
    float* q_s = sm + SM_QS;
    float* S_s = sm + SM_SS;
    float* v_s = sm + SM_VS;

    int bx = blockIdx.x;
    int gt = bx & 15, ot = (bx >> 4) & 7, n = bx >> 7;
    int o_base = ot * OB, g_base = gt * GBL;
    int tid = threadIdx.x;
    int o_l = tid & 15, glane = tid >> 4;
    int o0 = o_base + o_l;

    // load k (full n slice) + q tile, coalesced float4
    {
        const float4* kg = (const float4*)(g_k + n * T_ * H_);
        float4* k4 = (float4*)k_s;
#pragma unroll
        for (int i = 0; i < 4; i++) k4[tid + i * 512] = kg[tid + i * 512];
        if (tid < GBL * H_ / 4)
            ((float4*)q_s)[tid] = ((const float4*)(g_q + (n * T_ + g_base) * H_))[tid];
    }

    // per-thread Wr row (8 packed f32x2), acc init with br*Vsum
    ull w[8];
    {
        const ull* wp = (const ull*)(Wr + o0 * H_);
#pragma unroll
        for (int j = 0; j < 8; j++) w[j] = wp[j];
    }
    ull acc[13];
    {
        ull brd = dup2(br[o0]);
        const ull* vs = (const ull*)(g_vsum + (n * O_ + o0) * 32);
#pragma unroll
        for (int j = 0; j < 13; j++) acc[j] = fmul2(brd, vs[j]);
    }

    // prefetch v chunk 0 into buffer 0
    cp_v_chunk(n, o_base, 0, v_s);
    CP_COMMIT();
    __syncthreads();   // k_s / q_s visible

    // tanh lane mapping
    int hh = tid & 15, gg = tid >> 4;
    float qv = q_s[gg * H_ + hh];

    // tanh S(0) -> buffer 0
    {
        const float* kp = k_s + hh;
        float* so = S_s + gg * (TCH * H_) + hh;
#pragma unroll
        for (int tt = 0; tt < TCH; tt++) so[tt * H_] = tanh_fast(qv - kp[tt * H_]);
    }
    CP_WAIT0();
    __syncthreads();   // S0 + v0 ready

    for (int c = 0; c < NCHUNK; c++) {
        int b = c & 1;
        float* Sb = S_s + b * S_BUF;
        float* Vb = v_s + b * V_BUF;

        if (c + 1 < NCHUNK) {
            // prefetch v(c+1) + compute tanh S(c+1) into alternate buffers
            cp_v_chunk(n, o_base, c + 1, v_s + (b ^ 1) * V_BUF);
            CP_COMMIT();
            const float* kp = k_s + (c + 1) * TCH * H_ + hh;
            float* so = S_s + (b ^ 1) * S_BUF + gg * (TCH * H_) + hh;
#pragma unroll
            for (int tt = 0; tt < TCH; tt++) so[tt * H_] = tanh_fast(qv - kp[tt * H_]);
        }

        // phase C: A = Wr . S; acc += A * v
        const float* Sg = Sb + glane * (TCH * H_);
#pragma unroll
        for (int tt = 0; tt < TCH; tt++) {
            const ulonglong2* sp = (const ulonglong2*)(Sg + tt * H_);
            ulonglong2 s0 = sp[0], s1 = sp[1];
            ull a0 = fmul2(w[0], s0.x); a0 = ffma2(w[1], s0.y, a0);
            a0 = ffma2(w[2], s1.x, a0); a0 = ffma2(w[3], s1.y, a0);
            ulonglong2 s2 = sp[2], s3 = sp[3];
            ull a1 = fmul2(w[4], s2.x); a1 = ffma2(w[5], s2.y, a1);
            a1 = ffma2(w[6], s3.x, a1); a1 = ffma2(w[7], s3.y, a1);
            float2 u = unpack2(fadd2(a0, a1));
            ull Ad = dup2(u.x + u.y);
            const float* vrow = Vb + (tt * OB + o_l) * 28;
            const ulonglong2* vp = (const ulonglong2*)vrow;
#pragma unroll
            for (int j = 0; j < 6; j++) {
                ulonglong2 vv = vp[j];
                acc[2 * j]     = ffma2(Ad, vv.x, acc[2 * j]);
                acc[2 * j + 1] = ffma2(Ad, vv.y, acc[2 * j + 1]);
            }
            ull vlast = *(const ull*)(vrow + 24);
            acc[12] = ffma2(Ad, vlast, acc[12]);
        }
        CP_WAIT0();
        __syncthreads();
    }

    // epilogue: write y (padded 26) + BN partial stats
    int g = g_base + glane;
    float* yp = g_y + (((size_t)(n * O_ + o0)) * T_ + g) * 26;
    float sum = 0.f, sq = 0.f;
#pragma unroll
    for (int j = 0; j < 13; j++) {
        float2 u = unpack2(acc[j]);
        *(ull*)(yp + 2 * j) = acc[j];
        sum += u.x + u.y;
        sq  += u.x * u.x + u.y * u.y;
    }
    // pair (o, glane even/odd) within warp
    sum += __shfl_xor_sync(0xffffffffu, sum, 16);
    sq  += __shfl_xor_sync(0xffffffffu, sq, 16);
    float* red = sm;   // reuse smem (all loop reads done past final barrier)
    if (tid < 32) red[tid] = 0.f;
    __syncthreads();
    if ((tid & 16) == 0) {
        atomicAdd(&red[o_l], sum);
        atomicAdd(&red[16 + o_l], sq);
    }
    __syncthreads();
    if (tid < 16)       atomicAdd(&g_chsum[o_base + tid], red[tid]);
    else if (tid < 32)  atomicAdd(&g_chsq[o_base + tid - 16], red[tid]);
}

// ---------------- K4: BN + residual + ReLU ---------------------------------------
// 512 blocks = (n,o), 512 threads = g
__global__ void bn_kernel(const float* __restrict__ x,
                          const float* __restrict__ gamma, const float* __restrict__ beta,
                          float* __restrict__ out) {
    int bx = blockIdx.x;
    int n = bx >> 7, o = bx & 127;
    int g = threadIdx.x;
    float mu  = g_chsum[o] * (1.0f / YCNT);
    float var = g_chsq[o] * (1.0f / YCNT) - mu * mu;
    float r = rsqrtf(var + EPS_);
    float gam = gamma[o] * r;
    float bet = beta[o] - mu * gam;
    const float* yp = g_y + (((size_t)(n * O_ + o)) * T_ + g) * 26;
    const float* xp = x + (((size_t)(n * C_ + o)) * T_ + g) * V_;
    float* op = out + (((size_t)(n * O_ + o)) * T_ + g) * V_;
#pragma unroll
    for (int v = 0; v < V_; v++) {
        float val = yp[v] * gam + bet + xp[v];
        op[v] = fmaxf(val, 0.f);
    }
}

// ---------------- launcher --------------------------------------------------------
extern "C" void kernel_launch(void* const* d_in, const int* in_sizes, int n_in,
                              void* d_out, int out_size) {
    const float* x     = (const float*)d_in[0];
    const float* Wq    = (const float*)d_in[1];
    const float* bq    = (const float*)d_in[2];
    const float* Wk    = (const float*)d_in[3];
    const float* bk    = (const float*)d_in[4];
    const float* Wv    = (const float*)d_in[5];
    const float* bv    = (const float*)d_in[6];
    const float* Wr    = (const float*)d_in[7];
    const float* br    = (const float*)d_in[8];
    const float* gamma = (const float*)d_in[9];
    const float* beta  = (const float*)d_in[10];
    float* out = (float*)d_out;

    const int smem_bytes = SM_TOT * 4;   // 157696
    cudaFuncSetAttribute(attn_kernel, cudaFuncAttributeMaxDynamicSharedMemorySize, smem_bytes);

    wt_kernel<<<64, 256>>>(Wv);
    qk_kernel<<<N_ * T_, 128>>>(x, Wq, bq, Wk, bk);
    v_kernel<<<N_ * T_, 128>>>(x, bv);
    vsum_kernel<<<64, 256>>>();
    zero_kernel<<<1, 256>>>();
    attn_kernel<<<512, 512, smem_bytes>>>(Wr, br);
    bn_kernel<<<512, 512>>>(x, gamma, beta, out);
}